// round 11
// baseline (speedup 1.0000x reference)
#include <cuda_runtime.h>
#include <cuda_fp16.h>
#include <cstdint>
#include <cstddef>

#define NN    8192
#define EE    262144
#define FEATN 1386
#define HIDN  4096
#define CODEN 64
#define KP    1408       // FEATN padded to 64*22
#define KCH64 22         // gemm1 K chunks of 64

// ---------------- scratch (no allocation allowed) ----------------
__device__ __half g_Xh[NN * KP];         // fp16-rounded, padded X      (23 MB)
__device__ __half g_Wth[HIDN * KP];      // fp16 W1^T [N][K], padded    (11.5 MB)
__device__ __half g_thT[CODEN * HIDN];   // fp16 theta^T [64][4096]     (0.5 MB)
__device__ __half g_feat_h[NN * HIDN];   // fp16 copy of feat           (67 MB)
__device__ float  g_xt[NN * CODEN];      // xt = feat @ theta           (2 MB)
__device__ float  g_m[NN * CODEN];       // per-hyperedge aggregate     (2 MB)
__device__ int    g_BcntI[NN];
__device__ int    g_DcntI[NN];
__device__ int    g_Boff[NN + 1];
__device__ int    g_Doff[NN + 1];
__device__ int    g_Bcur[NN];
__device__ int    g_Dcur[NN];
__device__ int    g_Blist[EE];
__device__ int    g_Dlist[EE];

// ---------------- helpers ----------------
__device__ __forceinline__ void cp_async16(uint32_t smem, const void* gmem) {
    asm volatile("cp.async.cg.shared.global [%0], [%1], 16;\n" :: "r"(smem), "l"(gmem));
}
__device__ __forceinline__ void cp_commit() { asm volatile("cp.async.commit_group;\n"); }

__device__ __forceinline__ void mma_f16(float c[4], const uint32_t a[4], const uint32_t b[2]) {
    asm volatile(
        "mma.sync.aligned.m16n8k16.row.col.f32.f16.f16.f32 "
        "{%0,%1,%2,%3}, {%4,%5,%6,%7}, {%8,%9}, {%0,%1,%2,%3};\n"
        : "+f"(c[0]), "+f"(c[1]), "+f"(c[2]), "+f"(c[3])
        : "r"(a[0]), "r"(a[1]), "r"(a[2]), "r"(a[3]), "r"(b[0]), "r"(b[1]));
}

__device__ __forceinline__ void ldsm_x4(uint32_t r[4], uint32_t addr) {
    asm volatile("ldmatrix.sync.aligned.m8n8.x4.shared.b16 {%0,%1,%2,%3}, [%4];"
                 : "=r"(r[0]), "=r"(r[1]), "=r"(r[2]), "=r"(r[3]) : "r"(addr));
}

// ---------------- zero scratch ----------------
__global__ void zero_kernel() {
    int idx = blockIdx.x * blockDim.x + threadIdx.x;
    if (idx < NN * CODEN) g_xt[idx] = 0.f;
    if (idx < NN) { g_BcntI[idx] = 0; g_DcntI[idx] = 0; }
}

// ---------------- prepass: round X -> half, pad K ----------------
__global__ void round_x_h(const float* __restrict__ x) {
    int idx = blockIdx.x * 256 + threadIdx.x;
    if (idx >= NN * (KP / 2)) return;
    int row = idx / (KP / 2);
    int p   = idx - row * (KP / 2);
    int col = p * 2;
    __half2 h = __float2half2_rn(0.f);
    if (col < FEATN) {
        float2 v = *reinterpret_cast<const float2*>(x + (size_t)row * FEATN + col);
        h = __floats2half2_rn(v.x, v.y);
    }
    *reinterpret_cast<__half2*>(&g_Xh[(size_t)row * KP + col]) = h;
}

// ---------------- prepass: W1 -> half, transpose to [N][K], pad ----------------
__global__ void round_wt_h(const float* __restrict__ W) {
    __shared__ float ts[32][33];
    int kb = blockIdx.x * 32, nb = blockIdx.y * 32;
    int tx = threadIdx.x, ty = threadIdx.y;
    #pragma unroll
    for (int i = 0; i < 4; i++) {
        int k = kb + ty + i * 8;
        float v = 0.f;
        if (k < FEATN) v = W[(size_t)k * HIDN + nb + tx];
        ts[ty + i * 8][tx] = v;
    }
    __syncthreads();
    #pragma unroll
    for (int i = 0; i < 4; i++)
        g_Wth[(size_t)(nb + ty + i * 8) * KP + kb + tx] = __float2half_rn(ts[tx][ty + i * 8]);
}

// ---------------- prepass: theta -> half, transpose to [64][4096] ----------------
__global__ void round_th_h(const float* __restrict__ th) {
    __shared__ float ts[32][33];
    int kb = blockIdx.x * 32, nb = blockIdx.y * 32;
    int tx = threadIdx.x, ty = threadIdx.y;
    #pragma unroll
    for (int i = 0; i < 4; i++)
        ts[ty + i * 8][tx] = th[(size_t)(kb + ty + i * 8) * CODEN + nb + tx];
    __syncthreads();
    #pragma unroll
    for (int i = 0; i < 4; i++)
        g_thT[(size_t)(nb + ty + i * 8) * HIDN + kb + tx] = __float2half_rn(ts[tx][ty + i * 8]);
}

// ---------------- GEMM1: feat = relu(Xh @ Wth^T + b1) ----------------
// BM=128, BN=128, BK=64; 128 threads (4 warps, 2x2), warp tile 64x64, 2 CTAs/SM.
// 3-stage cp.async pipeline, one __syncthreads per chunk.
#define G1_AS     72
#define G1_BUFE   (128 * G1_AS)          // elems per A (or B) buffer
#define G1_STAGEE (2 * G1_BUFE)          // elems per stage (A then B)
#define G1_SMEM   (3 * G1_STAGEE * 2)    // bytes = 110592

__global__ __launch_bounds__(128, 2)
void gemm1_h(const float* __restrict__ bias1, float* __restrict__ feat) {
    constexpr int AS = G1_AS;
    extern __shared__ __half sm[];

    const int tid = threadIdx.x;
    const int m0 = blockIdx.y * 128;
    const int n0 = blockIdx.x * 128;

    const __half* Abase = g_Xh + (size_t)m0 * KP;
    const __half* Bbase = g_Wth + (size_t)n0 * KP;

    auto loadStage = [&](int st, int kc) {
        __half* sA = sm + st * G1_STAGEE;
        __half* sB = sA + G1_BUFE;
        #pragma unroll
        for (int i = 0; i < 8; i++) {
            int c = tid + i * 128;            // 0..1023
            int row = c >> 3, ch = c & 7;
            cp_async16((uint32_t)__cvta_generic_to_shared(&sA[row * AS + ch * 8]),
                       Abase + (size_t)row * KP + kc * 64 + ch * 8);
        }
        #pragma unroll
        for (int i = 0; i < 8; i++) {
            int c = tid + i * 128;
            int row = c >> 3, ch = c & 7;
            cp_async16((uint32_t)__cvta_generic_to_shared(&sB[row * AS + ch * 8]),
                       Bbase + (size_t)row * KP + kc * 64 + ch * 8);
        }
    };

    float acc[4][8][4];
    #pragma unroll
    for (int mi = 0; mi < 4; mi++)
        #pragma unroll
        for (int ni = 0; ni < 8; ni++)
            #pragma unroll
            for (int r = 0; r < 4; r++) acc[mi][ni][r] = 0.f;

    loadStage(0, 0); cp_commit();
    loadStage(1, 1); cp_commit();

    const int warp = tid >> 5, lane = tid & 31;
    const int wm = warp & 1, wn = warp >> 1;       // 2 x 2 warp grid
    const int mW = wm * 64, nW = wn * 64;          // warp tile 64 x 64
    const int g = lane >> 2, t = lane & 3;

    const int aRow = mW + (lane & 15);
    const int aK   = (lane >> 4) * 8;
    const int bRow = nW + ((lane >> 4) << 3) + (lane & 7);
    const int bK   = ((lane >> 3) & 1) * 8;

    int st = 0;
    for (int kt = 0; kt < KCH64; kt++) {
        if (kt < KCH64 - 1) asm volatile("cp.async.wait_group 1;\n");
        else                asm volatile("cp.async.wait_group 0;\n");
        __syncthreads();

        if (kt + 2 < KCH64) {
            int ns = st + 2; if (ns >= 3) ns -= 3;
            loadStage(ns, kt + 2);
            cp_commit();
        }

        const __half* A = sm + st * G1_STAGEE;
        const __half* B = A + G1_BUFE;
        uint32_t aAddr0 = (uint32_t)__cvta_generic_to_shared(&A[aRow * AS + aK]);
        uint32_t bAddr0 = (uint32_t)__cvta_generic_to_shared(&B[bRow * AS + bK]);
        #pragma unroll
        for (int ks = 0; ks < 4; ks++) {
            const uint32_t kOff = ks * 16 * 2;
            uint32_t af[4][4], bf[8][2];
            #pragma unroll
            for (int mi = 0; mi < 4; mi++)
                ldsm_x4(af[mi], aAddr0 + kOff + mi * 16 * AS * 2);
            #pragma unroll
            for (int p = 0; p < 4; p++) {
                uint32_t r[4];
                ldsm_x4(r, bAddr0 + kOff + p * 16 * AS * 2);
                bf[2 * p][0] = r[0]; bf[2 * p][1] = r[1];
                bf[2 * p + 1][0] = r[2]; bf[2 * p + 1][1] = r[3];
            }
            #pragma unroll
            for (int mi = 0; mi < 4; mi++)
                #pragma unroll
                for (int ni = 0; ni < 8; ni++)
                    mma_f16(acc[mi][ni], af[mi], bf[ni]);
        }
        if (++st == 3) st = 0;
    }

    // epilogue: +bias, relu, store fp32 feat + fp16 copy
    #pragma unroll
    for (int mi = 0; mi < 4; mi++) {
        #pragma unroll
        for (int ni = 0; ni < 8; ni++) {
            int col = n0 + nW + ni * 8 + t * 2;
            float bv0 = bias1[col], bv1 = bias1[col + 1];
            int r0 = m0 + mW + mi * 16 + g;
            float v0 = fmaxf(acc[mi][ni][0] + bv0, 0.f);
            float v1 = fmaxf(acc[mi][ni][1] + bv1, 0.f);
            *reinterpret_cast<float2*>(&feat[(size_t)r0 * HIDN + col]) = make_float2(v0, v1);
            *reinterpret_cast<__half2*>(&g_feat_h[(size_t)r0 * HIDN + col]) = __floats2half2_rn(v0, v1);
            float v2 = fmaxf(acc[mi][ni][2] + bv0, 0.f);
            float v3 = fmaxf(acc[mi][ni][3] + bv1, 0.f);
            *reinterpret_cast<float2*>(&feat[(size_t)(r0 + 8) * HIDN + col]) = make_float2(v2, v3);
            *reinterpret_cast<__half2*>(&g_feat_h[(size_t)(r0 + 8) * HIDN + col]) = __floats2half2_rn(v2, v3);
        }
    }
}

// ---------------- GEMM2: xt = feat_h @ thT^T ----------
// BM=128, BN=64, BK=64, split-K = 4 x 1024; 3-stage, single-sync.
#define G2_AS     72
#define G2_ABUFE  (128 * G2_AS)
#define G2_BBUFE  (64 * G2_AS)
#define G2_STAGEE (G2_ABUFE + G2_BBUFE)
#define G2_SMEM   (3 * G2_STAGEE * 2)    // bytes = 82944

__global__ __launch_bounds__(256, 2)
void gemm2_h() {
    constexpr int AS = G2_AS;
    extern __shared__ __half sm2[];

    const int tid = threadIdx.x;
    const int m0 = blockIdx.y * 128;
    const int kbase = blockIdx.x * 1024;
    const int KT = 1024 / 64;   // 16

    const __half* Abase = g_feat_h + (size_t)m0 * HIDN + kbase;

    auto loadStage = [&](int st, int kc) {
        __half* sA = sm2 + st * G2_STAGEE;
        __half* sB = sA + G2_ABUFE;
        #pragma unroll
        for (int i = 0; i < 4; i++) {
            int c = tid + i * 256;            // 0..1023
            int row = c >> 3, ch = c & 7;
            cp_async16((uint32_t)__cvta_generic_to_shared(&sA[row * AS + ch * 8]),
                       Abase + (size_t)row * HIDN + kc * 64 + ch * 8);
        }
        #pragma unroll
        for (int i = 0; i < 2; i++) {
            int c = tid + i * 256;            // 0..511
            int row = c >> 3, ch = c & 7;
            cp_async16((uint32_t)__cvta_generic_to_shared(&sB[row * AS + ch * 8]),
                       g_thT + (size_t)row * HIDN + kbase + kc * 64 + ch * 8);
        }
    };

    float acc[2][4][4];
    #pragma unroll
    for (int mi = 0; mi < 2; mi++)
        #pragma unroll
        for (int ni = 0; ni < 4; ni++)
            #pragma unroll
            for (int r = 0; r < 4; r++) acc[mi][ni][r] = 0.f;

    loadStage(0, 0); cp_commit();
    loadStage(1, 1); cp_commit();

    const int warp = tid >> 5, lane = tid & 31;
    const int wm = warp & 3, wn = warp >> 2;
    const int mW = wm * 32, nW = wn * 32;
    const int g = lane >> 2, t = lane & 3;

    const int aRow = mW + (lane & 15);
    const int aK   = (lane >> 4) * 8;
    const int bRow = nW + ((lane >> 4) << 3) + (lane & 7);
    const int bK   = ((lane >> 3) & 1) * 8;

    int st = 0;
    for (int kt = 0; kt < KT; kt++) {
        if (kt < KT - 1) asm volatile("cp.async.wait_group 1;\n");
        else             asm volatile("cp.async.wait_group 0;\n");
        __syncthreads();

        if (kt + 2 < KT) {
            int ns = st + 2; if (ns >= 3) ns -= 3;
            loadStage(ns, kt + 2);
            cp_commit();
        }

        const __half* A = sm2 + st * G2_STAGEE;
        const __half* B = A + G2_ABUFE;
        uint32_t aAddr0 = (uint32_t)__cvta_generic_to_shared(&A[aRow * AS + aK]);
        uint32_t bAddr0 = (uint32_t)__cvta_generic_to_shared(&B[bRow * AS + bK]);
        #pragma unroll
        for (int ks = 0; ks < 4; ks++) {
            const uint32_t kOff = ks * 16 * 2;
            uint32_t af[2][4], bf[4][2];
            #pragma unroll
            for (int mi = 0; mi < 2; mi++)
                ldsm_x4(af[mi], aAddr0 + kOff + mi * 16 * AS * 2);
            #pragma unroll
            for (int p = 0; p < 2; p++) {
                uint32_t r[4];
                ldsm_x4(r, bAddr0 + kOff + p * 16 * AS * 2);
                bf[2 * p][0] = r[0]; bf[2 * p][1] = r[1];
                bf[2 * p + 1][0] = r[2]; bf[2 * p + 1][1] = r[3];
            }
            #pragma unroll
            for (int mi = 0; mi < 2; mi++)
                #pragma unroll
                for (int ni = 0; ni < 4; ni++)
                    mma_f16(acc[mi][ni], af[mi], bf[ni]);
        }
        if (++st == 3) st = 0;
    }

    #pragma unroll
    for (int mi = 0; mi < 2; mi++) {
        #pragma unroll
        for (int ni = 0; ni < 4; ni++) {
            int col = nW + ni * 8 + t * 2;
            int r0 = m0 + mW + mi * 16 + g;
            atomicAdd(&g_xt[(size_t)r0 * CODEN + col    ], acc[mi][ni][0]);
            atomicAdd(&g_xt[(size_t)r0 * CODEN + col + 1], acc[mi][ni][1]);
            atomicAdd(&g_xt[(size_t)(r0 + 8) * CODEN + col    ], acc[mi][ni][2]);
            atomicAdd(&g_xt[(size_t)(r0 + 8) * CODEN + col + 1], acc[mi][ni][3]);
        }
    }
}

// ---------------- CSR build ----------------
__global__ void degree_kernel(const int* __restrict__ node, const int* __restrict__ edge) {
    int i = blockIdx.x * blockDim.x + threadIdx.x;
    if (i < EE) {
        atomicAdd(&g_DcntI[node[i]], 1);
        atomicAdd(&g_BcntI[edge[i]], 1);
    }
}

__global__ void scan_kernel() {
    const int* cnt = blockIdx.x ? g_DcntI : g_BcntI;
    int* off = blockIdx.x ? g_Doff : g_Boff;
    int* cur = blockIdx.x ? g_Dcur : g_Bcur;
    __shared__ int part[1024];
    int t = threadIdx.x;
    int base = t * 8;
    int loc[8];
    int s = 0;
    #pragma unroll
    for (int i = 0; i < 8; i++) { loc[i] = s; s += cnt[base + i]; }
    part[t] = s;
    __syncthreads();
    for (int ofs = 1; ofs < 1024; ofs <<= 1) {
        int v = (t >= ofs) ? part[t - ofs] : 0;
        __syncthreads();
        part[t] += v;
        __syncthreads();
    }
    int prev = (t == 0) ? 0 : part[t - 1];
    #pragma unroll
    for (int i = 0; i < 8; i++) { off[base + i] = prev + loc[i]; cur[base + i] = prev + loc[i]; }
    if (t == 1023) off[NN] = part[1023];
}

__global__ void fill_kernel(const int* __restrict__ node, const int* __restrict__ edge) {
    int i = blockIdx.x * blockDim.x + threadIdx.x;
    if (i >= EE) return;
    int n = node[i], e = edge[i];
    int p = atomicAdd(&g_Bcur[e], 1);
    g_Blist[p] = n;
    int q = atomicAdd(&g_Dcur[n], 1);
    g_Dlist[q] = e;
}

// ---------------- gathers (16 threads/segment, float4 lanes) ----------
__global__ void gather1_kernel() {
    int seg = blockIdx.x * 16 + (threadIdx.x >> 4);   // hyperedge id
    int q   = threadIdx.x & 15;
    int s = g_Boff[seg], t = g_Boff[seg + 1];
    float4 acc = make_float4(0.f, 0.f, 0.f, 0.f);
    int j = s;
    for (; j + 1 < t; j += 2) {
        int n0 = g_Blist[j], n1 = g_Blist[j + 1];
        float4 v0 = reinterpret_cast<const float4*>(g_xt)[n0 * 16 + q];
        float4 v1 = reinterpret_cast<const float4*>(g_xt)[n1 * 16 + q];
        acc.x += v0.x + v1.x; acc.y += v0.y + v1.y;
        acc.z += v0.z + v1.z; acc.w += v0.w + v1.w;
    }
    if (j < t) {
        float4 v = reinterpret_cast<const float4*>(g_xt)[g_Blist[j] * 16 + q];
        acc.x += v.x; acc.y += v.y; acc.z += v.z; acc.w += v.w;
    }
    float binv = (t > s) ? 1.f / (float)(t - s) : 0.f;
    acc.x *= binv; acc.y *= binv; acc.z *= binv; acc.w *= binv;
    reinterpret_cast<float4*>(g_m)[seg * 16 + q] = acc;
}

__global__ void gather2_kernel(float* __restrict__ hid, float* __restrict__ code,
                               const float* __restrict__ bias) {
    int seg = blockIdx.x * 16 + (threadIdx.x >> 4);   // node id
    int q   = threadIdx.x & 15;
    int s = g_Doff[seg], t = g_Doff[seg + 1];
    float4 acc = make_float4(0.f, 0.f, 0.f, 0.f);
    int j = s;
    for (; j + 1 < t; j += 2) {
        int e0 = g_Dlist[j], e1 = g_Dlist[j + 1];
        float4 v0 = reinterpret_cast<const float4*>(g_m)[e0 * 16 + q];
        float4 v1 = reinterpret_cast<const float4*>(g_m)[e1 * 16 + q];
        acc.x += v0.x + v1.x; acc.y += v0.y + v1.y;
        acc.z += v0.z + v1.z; acc.w += v0.w + v1.w;
    }
    if (j < t) {
        float4 v = reinterpret_cast<const float4*>(g_m)[g_Dlist[j] * 16 + q];
        acc.x += v.x; acc.y += v.y; acc.z += v.z; acc.w += v.w;
    }
    float dinv = (t > s) ? 1.f / (float)(t - s) : 0.f;
    float4 b = reinterpret_cast<const float4*>(bias)[q];
    float4 h;
    h.x = acc.x * dinv + b.x;
    h.y = acc.y * dinv + b.y;
    h.z = acc.z * dinv + b.z;
    h.w = acc.w * dinv + b.w;
    reinterpret_cast<float4*>(hid)[seg * 16 + q] = h;
    float4 c;
    c.x = tanhf(h.x); c.y = tanhf(h.y); c.z = tanhf(h.z); c.w = tanhf(h.w);
    reinterpret_cast<float4*>(code)[seg * 16 + q] = c;
}

// ---------------- launch ----------------
extern "C" void kernel_launch(void* const* d_in, const int* in_sizes, int n_in,
                              void* d_out, int out_size) {
    const float* x     = (const float*)d_in[0];
    const float* W1    = (const float*)d_in[1];
    const float* b1    = (const float*)d_in[2];
    const float* theta = (const float*)d_in[3];
    const float* bias  = (const float*)d_in[4];
    const int*   hidx  = (const int*)d_in[5];
    const int* node = hidx;
    const int* edge = hidx + EE;

    float* out  = (float*)d_out;
    float* feat = out;
    float* hid  = out + (size_t)NN * HIDN;
    float* code = hid + (size_t)NN * CODEN;

    static bool attr_done = false;
    if (!attr_done) {
        cudaFuncSetAttribute(gemm1_h, cudaFuncAttributeMaxDynamicSharedMemorySize, G1_SMEM);
        cudaFuncSetAttribute(gemm2_h, cudaFuncAttributeMaxDynamicSharedMemorySize, G2_SMEM);
        attr_done = true;
    }

    // gemm1 placed early so the fixed ncu window (-s 5 -c 1) can catch it
    zero_kernel<<<(NN * CODEN + 255) / 256, 256>>>();
    round_x_h<<<(NN * (KP / 2) + 255) / 256, 256>>>(x);
    round_wt_h<<<dim3(KP / 32, HIDN / 32), dim3(32, 8)>>>(W1);
    gemm1_h<<<dim3(HIDN / 128, NN / 128), 128, G1_SMEM>>>(b1, feat);
    round_th_h<<<dim3(HIDN / 32, CODEN / 32), dim3(32, 8)>>>(theta);
    degree_kernel<<<(EE + 255) / 256, 256>>>(node, edge);
    scan_kernel<<<2, 1024>>>();
    fill_kernel<<<(EE + 255) / 256, 256>>>(node, edge);
    gemm2_h<<<dim3(4, NN / 128), 256, G2_SMEM>>>();
    gather1_kernel<<<NN / 16, 256>>>();
    gather2_kernel<<<NN / 16, 256>>>(hid, code, bias);
}

// round 12
// speedup vs baseline: 1.1474x; 1.1474x over previous
#include <cuda_runtime.h>
#include <cuda_fp16.h>
#include <cstdint>
#include <cstddef>

#define NN    8192
#define EE    262144
#define FEATN 1386
#define HIDN  4096
#define CODEN 64
#define KP    1408       // FEATN padded to 64*22
#define KCH64 22         // gemm1 K chunks of 64

// ---------------- scratch (no allocation allowed) ----------------
__device__ __half g_Xh[NN * KP];         // fp16-rounded, padded X      (23 MB)
__device__ __half g_Wth[HIDN * KP];      // fp16 W1^T [N][K], padded    (11.5 MB)
__device__ __half g_thT[CODEN * HIDN];   // fp16 theta^T [64][4096]     (0.5 MB)
__device__ __half g_feat_h[NN * HIDN];   // fp16 copy of feat           (67 MB)
__device__ float  g_xt[NN * CODEN];      // xt = feat @ theta           (2 MB)
__device__ float  g_m[NN * CODEN];       // per-hyperedge aggregate     (2 MB)
__device__ int    g_BcntI[NN];
__device__ int    g_DcntI[NN];
__device__ int    g_Boff[NN + 1];
__device__ int    g_Doff[NN + 1];
__device__ int    g_Bcur[NN];
__device__ int    g_Dcur[NN];
__device__ int    g_Blist[EE];
__device__ int    g_Dlist[EE];

// ---------------- helpers ----------------
__device__ __forceinline__ void cp_async16(uint32_t smem, const void* gmem) {
    asm volatile("cp.async.cg.shared.global [%0], [%1], 16;\n" :: "r"(smem), "l"(gmem));
}
__device__ __forceinline__ void cp_commit() { asm volatile("cp.async.commit_group;\n"); }

__device__ __forceinline__ void mma_f16(float c[4], const uint32_t a[4], const uint32_t b[2]) {
    asm volatile(
        "mma.sync.aligned.m16n8k16.row.col.f32.f16.f16.f32 "
        "{%0,%1,%2,%3}, {%4,%5,%6,%7}, {%8,%9}, {%0,%1,%2,%3};\n"
        : "+f"(c[0]), "+f"(c[1]), "+f"(c[2]), "+f"(c[3])
        : "r"(a[0]), "r"(a[1]), "r"(a[2]), "r"(a[3]), "r"(b[0]), "r"(b[1]));
}

__device__ __forceinline__ void ldsm_x4(uint32_t r[4], uint32_t addr) {
    asm volatile("ldmatrix.sync.aligned.m8n8.x4.shared.b16 {%0,%1,%2,%3}, [%4];"
                 : "=r"(r[0]), "=r"(r[1]), "=r"(r[2]), "=r"(r[3]) : "r"(addr));
}

// ---------------- zero scratch ----------------
__global__ void zero_kernel() {
    int idx = blockIdx.x * blockDim.x + threadIdx.x;
    if (idx < NN * CODEN) g_xt[idx] = 0.f;
    if (idx < NN) { g_BcntI[idx] = 0; g_DcntI[idx] = 0; }
}

// ---------------- prepass: round X -> half, pad K ----------------
__global__ void round_x_h(const float* __restrict__ x) {
    int idx = blockIdx.x * 256 + threadIdx.x;
    if (idx >= NN * (KP / 2)) return;
    int row = idx / (KP / 2);
    int p   = idx - row * (KP / 2);
    int col = p * 2;
    __half2 h = __float2half2_rn(0.f);
    if (col < FEATN) {
        float2 v = *reinterpret_cast<const float2*>(x + (size_t)row * FEATN + col);
        h = __floats2half2_rn(v.x, v.y);
    }
    *reinterpret_cast<__half2*>(&g_Xh[(size_t)row * KP + col]) = h;
}

// ---------------- prepass: W1 -> half, transpose to [N][K], pad ----------------
__global__ void round_wt_h(const float* __restrict__ W) {
    __shared__ float ts[32][33];
    int kb = blockIdx.x * 32, nb = blockIdx.y * 32;
    int tx = threadIdx.x, ty = threadIdx.y;
    #pragma unroll
    for (int i = 0; i < 4; i++) {
        int k = kb + ty + i * 8;
        float v = 0.f;
        if (k < FEATN) v = W[(size_t)k * HIDN + nb + tx];
        ts[ty + i * 8][tx] = v;
    }
    __syncthreads();
    #pragma unroll
    for (int i = 0; i < 4; i++)
        g_Wth[(size_t)(nb + ty + i * 8) * KP + kb + tx] = __float2half_rn(ts[tx][ty + i * 8]);
}

// ---------------- prepass: theta -> half, transpose to [64][4096] ----------------
__global__ void round_th_h(const float* __restrict__ th) {
    __shared__ float ts[32][33];
    int kb = blockIdx.x * 32, nb = blockIdx.y * 32;
    int tx = threadIdx.x, ty = threadIdx.y;
    #pragma unroll
    for (int i = 0; i < 4; i++)
        ts[ty + i * 8][tx] = th[(size_t)(kb + ty + i * 8) * CODEN + nb + tx];
    __syncthreads();
    #pragma unroll
    for (int i = 0; i < 4; i++)
        g_thT[(size_t)(nb + ty + i * 8) * HIDN + kb + tx] = __float2half_rn(ts[tx][ty + i * 8]);
}

// ---------------- GEMM1: feat = relu(Xh @ Wth^T + b1) ----------------
// BM=128, BN=128, BK=64; 128 threads (4 warps, 2x2), warp tile 64x64, 2 CTAs/SM.
// Double-buffered smem (R10) + register fragment double-buffering.
#define G1_AS    72
#define G1_BUF   (128 * G1_AS)
#define G1_SMEM  (4 * G1_BUF * 2)     // bytes = 73728

__global__ __launch_bounds__(128, 2)
void gemm1_h(const float* __restrict__ bias1, float* __restrict__ feat) {
    constexpr int AS = G1_AS;
    extern __shared__ __half sm[];
    __half* sA[2] = { sm, sm + G1_BUF };
    __half* sB[2] = { sm + 2 * G1_BUF, sm + 3 * G1_BUF };

    const int tid = threadIdx.x;
    const int m0 = blockIdx.y * 128;
    const int n0 = blockIdx.x * 128;

    const __half* Abase = g_Xh + (size_t)m0 * KP;
    const __half* Bbase = g_Wth + (size_t)n0 * KP;

    auto loadA = [&](int buf, int kc) {
        #pragma unroll
        for (int i = 0; i < 8; i++) {
            int c = tid + i * 128;            // 0..1023
            int row = c >> 3, ch = c & 7;
            cp_async16((uint32_t)__cvta_generic_to_shared(&sA[buf][row * AS + ch * 8]),
                       Abase + (size_t)row * KP + kc * 64 + ch * 8);
        }
    };
    auto loadB = [&](int buf, int kc) {
        #pragma unroll
        for (int i = 0; i < 8; i++) {
            int c = tid + i * 128;
            int row = c >> 3, ch = c & 7;
            cp_async16((uint32_t)__cvta_generic_to_shared(&sB[buf][row * AS + ch * 8]),
                       Bbase + (size_t)row * KP + kc * 64 + ch * 8);
        }
    };

    float acc[4][8][4];
    #pragma unroll
    for (int mi = 0; mi < 4; mi++)
        #pragma unroll
        for (int ni = 0; ni < 8; ni++)
            #pragma unroll
            for (int r = 0; r < 4; r++) acc[mi][ni][r] = 0.f;

    loadA(0, 0); loadB(0, 0); cp_commit();

    const int warp = tid >> 5, lane = tid & 31;
    const int wm = warp & 1, wn = warp >> 1;       // 2 x 2 warp grid
    const int mW = wm * 64, nW = wn * 64;          // warp tile 64 x 64
    const int g = lane >> 2, t = lane & 3;

    const int aRow = mW + (lane & 15);
    const int aK   = (lane >> 4) * 8;
    const int bRow = nW + ((lane >> 4) << 3) + (lane & 7);
    const int bK   = ((lane >> 3) & 1) * 8;

    // register fragment double buffer
    uint32_t af[2][4][4], bf[2][8][2];

    auto loadFrags = [&](uint32_t aAddr0, uint32_t bAddr0, int ks, int slot) {
        const uint32_t kOff = (uint32_t)ks * 32;   // 16 halves * 2 B
        #pragma unroll
        for (int mi = 0; mi < 4; mi++)
            ldsm_x4(af[slot][mi], aAddr0 + kOff + mi * 16 * AS * 2);
        #pragma unroll
        for (int p = 0; p < 4; p++) {
            uint32_t r[4];
            ldsm_x4(r, bAddr0 + kOff + p * 16 * AS * 2);
            bf[slot][2 * p][0] = r[0]; bf[slot][2 * p][1] = r[1];
            bf[slot][2 * p + 1][0] = r[2]; bf[slot][2 * p + 1][1] = r[3];
        }
    };

    int buf = 0;
    for (int kt = 0; kt < KCH64; kt++) {
        if (kt + 1 < KCH64) {
            loadA(buf ^ 1, kt + 1);
            loadB(buf ^ 1, kt + 1);
            cp_commit();
            asm volatile("cp.async.wait_group 1;\n");
        } else {
            asm volatile("cp.async.wait_group 0;\n");
        }
        __syncthreads();

        const __half* A = sA[buf];
        const __half* B = sB[buf];
        uint32_t aAddr0 = (uint32_t)__cvta_generic_to_shared(&A[aRow * AS + aK]);
        uint32_t bAddr0 = (uint32_t)__cvta_generic_to_shared(&B[bRow * AS + bK]);

        loadFrags(aAddr0, bAddr0, 0, 0);
        #pragma unroll
        for (int ks = 0; ks < 4; ks++) {
            const int cur = ks & 1;
            if (ks < 3) loadFrags(aAddr0, bAddr0, ks + 1, cur ^ 1);
            #pragma unroll
            for (int mi = 0; mi < 4; mi++)
                #pragma unroll
                for (int ni = 0; ni < 8; ni++)
                    mma_f16(acc[mi][ni], af[cur][mi], bf[cur][ni]);
        }
        __syncthreads();
        buf ^= 1;
    }

    // epilogue: +bias, relu, store fp32 feat + fp16 copy
    #pragma unroll
    for (int mi = 0; mi < 4; mi++) {
        #pragma unroll
        for (int ni = 0; ni < 8; ni++) {
            int col = n0 + nW + ni * 8 + t * 2;
            float bv0 = bias1[col], bv1 = bias1[col + 1];
            int r0 = m0 + mW + mi * 16 + g;
            float v0 = fmaxf(acc[mi][ni][0] + bv0, 0.f);
            float v1 = fmaxf(acc[mi][ni][1] + bv1, 0.f);
            *reinterpret_cast<float2*>(&feat[(size_t)r0 * HIDN + col]) = make_float2(v0, v1);
            *reinterpret_cast<__half2*>(&g_feat_h[(size_t)r0 * HIDN + col]) = __floats2half2_rn(v0, v1);
            float v2 = fmaxf(acc[mi][ni][2] + bv0, 0.f);
            float v3 = fmaxf(acc[mi][ni][3] + bv1, 0.f);
            *reinterpret_cast<float2*>(&feat[(size_t)(r0 + 8) * HIDN + col]) = make_float2(v2, v3);
            *reinterpret_cast<__half2*>(&g_feat_h[(size_t)(r0 + 8) * HIDN + col]) = __floats2half2_rn(v2, v3);
        }
    }
}

// ---------------- GEMM2: xt = feat_h @ thT^T, fp16 mma + ldmatrix ----------
// BM=128, BN=64, BK=64, split-K = 4 x 1024. Double-buffered (R10).
#define G2_AS    72
#define G2_ABUF  (128 * G2_AS)
#define G2_BBUF  (64 * G2_AS)
#define G2_SMEM  ((2 * G2_ABUF + 2 * G2_BBUF) * 2)   // bytes = 55296

__global__ __launch_bounds__(256, 2)
void gemm2_h() {
    constexpr int AS = G2_AS;
    extern __shared__ __half sm2[];
    __half* sA[2] = { sm2, sm2 + G2_ABUF };
    __half* sB[2] = { sm2 + 2 * G2_ABUF, sm2 + 2 * G2_ABUF + G2_BBUF };

    const int tid = threadIdx.x;
    const int m0 = blockIdx.y * 128;
    const int kbase = blockIdx.x * 1024;
    const int KT = 1024 / 64;   // 16

    const __half* Abase = g_feat_h + (size_t)m0 * HIDN + kbase;

    auto loadA = [&](int buf, int kc) {
        #pragma unroll
        for (int i = 0; i < 4; i++) {
            int c = tid + i * 256;            // 0..1023
            int row = c >> 3, ch = c & 7;
            cp_async16((uint32_t)__cvta_generic_to_shared(&sA[buf][row * AS + ch * 8]),
                       Abase + (size_t)row * HIDN + kc * 64 + ch * 8);
        }
    };
    auto loadB = [&](int buf, int kc) {
        #pragma unroll
        for (int i = 0; i < 2; i++) {
            int c = tid + i * 256;            // 0..511
            int row = c >> 3, ch = c & 7;
            cp_async16((uint32_t)__cvta_generic_to_shared(&sB[buf][row * AS + ch * 8]),
                       g_thT + (size_t)row * HIDN + kbase + kc * 64 + ch * 8);
        }
    };

    float acc[2][4][4];
    #pragma unroll
    for (int mi = 0; mi < 2; mi++)
        #pragma unroll
        for (int ni = 0; ni < 4; ni++)
            #pragma unroll
            for (int r = 0; r < 4; r++) acc[mi][ni][r] = 0.f;

    loadA(0, 0); loadB(0, 0); cp_commit();

    const int warp = tid >> 5, lane = tid & 31;
    const int wm = warp & 3, wn = warp >> 2;
    const int mW = wm * 32, nW = wn * 32;
    const int g = lane >> 2, t = lane & 3;

    const int aRow = mW + (lane & 15);
    const int aK   = (lane >> 4) * 8;
    const int bRow = nW + ((lane >> 4) << 3) + (lane & 7);
    const int bK   = ((lane >> 3) & 1) * 8;

    int buf = 0;
    for (int kt = 0; kt < KT; kt++) {
        if (kt + 1 < KT) {
            loadA(buf ^ 1, kt + 1);
            loadB(buf ^ 1, kt + 1);
            cp_commit();
            asm volatile("cp.async.wait_group 1;\n");
        } else {
            asm volatile("cp.async.wait_group 0;\n");
        }
        __syncthreads();

        const __half* A = sA[buf];
        const __half* B = sB[buf];
        uint32_t aAddr0 = (uint32_t)__cvta_generic_to_shared(&A[aRow * AS + aK]);
        uint32_t bAddr0 = (uint32_t)__cvta_generic_to_shared(&B[bRow * AS + bK]);
        #pragma unroll
        for (int ks = 0; ks < 4; ks++) {
            const uint32_t kOff = ks * 16 * 2;
            uint32_t af[2][4], bf[4][2];
            #pragma unroll
            for (int mi = 0; mi < 2; mi++)
                ldsm_x4(af[mi], aAddr0 + kOff + mi * 16 * AS * 2);
            #pragma unroll
            for (int p = 0; p < 2; p++) {
                uint32_t r[4];
                ldsm_x4(r, bAddr0 + kOff + p * 16 * AS * 2);
                bf[2 * p][0] = r[0]; bf[2 * p][1] = r[1];
                bf[2 * p + 1][0] = r[2]; bf[2 * p + 1][1] = r[3];
            }
            #pragma unroll
            for (int mi = 0; mi < 2; mi++)
                #pragma unroll
                for (int ni = 0; ni < 4; ni++)
                    mma_f16(acc[mi][ni], af[mi], bf[ni]);
        }
        __syncthreads();
        buf ^= 1;
    }

    #pragma unroll
    for (int mi = 0; mi < 2; mi++) {
        #pragma unroll
        for (int ni = 0; ni < 4; ni++) {
            int col = nW + ni * 8 + t * 2;
            int r0 = m0 + mW + mi * 16 + g;
            atomicAdd(&g_xt[(size_t)r0 * CODEN + col    ], acc[mi][ni][0]);
            atomicAdd(&g_xt[(size_t)r0 * CODEN + col + 1], acc[mi][ni][1]);
            atomicAdd(&g_xt[(size_t)(r0 + 8) * CODEN + col    ], acc[mi][ni][2]);
            atomicAdd(&g_xt[(size_t)(r0 + 8) * CODEN + col + 1], acc[mi][ni][3]);
        }
    }
}

// ---------------- CSR build ----------------
__global__ void degree_kernel(const int* __restrict__ node, const int* __restrict__ edge) {
    int i = blockIdx.x * blockDim.x + threadIdx.x;
    if (i < EE) {
        atomicAdd(&g_DcntI[node[i]], 1);
        atomicAdd(&g_BcntI[edge[i]], 1);
    }
}

__global__ void scan_kernel() {
    const int* cnt = blockIdx.x ? g_DcntI : g_BcntI;
    int* off = blockIdx.x ? g_Doff : g_Boff;
    int* cur = blockIdx.x ? g_Dcur : g_Bcur;
    __shared__ int part[1024];
    int t = threadIdx.x;
    int base = t * 8;
    int loc[8];
    int s = 0;
    #pragma unroll
    for (int i = 0; i < 8; i++) { loc[i] = s; s += cnt[base + i]; }
    part[t] = s;
    __syncthreads();
    for (int ofs = 1; ofs < 1024; ofs <<= 1) {
        int v = (t >= ofs) ? part[t - ofs] : 0;
        __syncthreads();
        part[t] += v;
        __syncthreads();
    }
    int prev = (t == 0) ? 0 : part[t - 1];
    #pragma unroll
    for (int i = 0; i < 8; i++) { off[base + i] = prev + loc[i]; cur[base + i] = prev + loc[i]; }
    if (t == 1023) off[NN] = part[1023];
}

__global__ void fill_kernel(const int* __restrict__ node, const int* __restrict__ edge) {
    int i = blockIdx.x * blockDim.x + threadIdx.x;
    if (i >= EE) return;
    int n = node[i], e = edge[i];
    int p = atomicAdd(&g_Bcur[e], 1);
    g_Blist[p] = n;
    int q = atomicAdd(&g_Dcur[n], 1);
    g_Dlist[q] = e;
}

// ---------------- gathers (16 threads/segment, float4 lanes) ----------
__global__ void gather1_kernel() {
    int seg = blockIdx.x * 16 + (threadIdx.x >> 4);   // hyperedge id
    int q   = threadIdx.x & 15;
    int s = g_Boff[seg], t = g_Boff[seg + 1];
    float4 acc = make_float4(0.f, 0.f, 0.f, 0.f);
    int j = s;
    for (; j + 1 < t; j += 2) {
        int n0 = g_Blist[j], n1 = g_Blist[j + 1];
        float4 v0 = reinterpret_cast<const float4*>(g_xt)[n0 * 16 + q];
        float4 v1 = reinterpret_cast<const float4*>(g_xt)[n1 * 16 + q];
        acc.x += v0.x + v1.x; acc.y += v0.y + v1.y;
        acc.z += v0.z + v1.z; acc.w += v0.w + v1.w;
    }
    if (j < t) {
        float4 v = reinterpret_cast<const float4*>(g_xt)[g_Blist[j] * 16 + q];
        acc.x += v.x; acc.y += v.y; acc.z += v.z; acc.w += v.w;
    }
    float binv = (t > s) ? 1.f / (float)(t - s) : 0.f;
    acc.x *= binv; acc.y *= binv; acc.z *= binv; acc.w *= binv;
    reinterpret_cast<float4*>(g_m)[seg * 16 + q] = acc;
}

__global__ void gather2_kernel(float* __restrict__ hid, float* __restrict__ code,
                               const float* __restrict__ bias) {
    int seg = blockIdx.x * 16 + (threadIdx.x >> 4);   // node id
    int q   = threadIdx.x & 15;
    int s = g_Doff[seg], t = g_Doff[seg + 1];
    float4 acc = make_float4(0.f, 0.f, 0.f, 0.f);
    int j = s;
    for (; j + 1 < t; j += 2) {
        int e0 = g_Dlist[j], e1 = g_Dlist[j + 1];
        float4 v0 = reinterpret_cast<const float4*>(g_m)[e0 * 16 + q];
        float4 v1 = reinterpret_cast<const float4*>(g_m)[e1 * 16 + q];
        acc.x += v0.x + v1.x; acc.y += v0.y + v1.y;
        acc.z += v0.z + v1.z; acc.w += v0.w + v1.w;
    }
    if (j < t) {
        float4 v = reinterpret_cast<const float4*>(g_m)[g_Dlist[j] * 16 + q];
        acc.x += v.x; acc.y += v.y; acc.z += v.z; acc.w += v.w;
    }
    float dinv = (t > s) ? 1.f / (float)(t - s) : 0.f;
    float4 b = reinterpret_cast<const float4*>(bias)[q];
    float4 h;
    h.x = acc.x * dinv + b.x;
    h.y = acc.y * dinv + b.y;
    h.z = acc.z * dinv + b.z;
    h.w = acc.w * dinv + b.w;
    reinterpret_cast<float4*>(hid)[seg * 16 + q] = h;
    float4 c;
    c.x = tanhf(h.x); c.y = tanhf(h.y); c.z = tanhf(h.z); c.w = tanhf(h.w);
    reinterpret_cast<float4*>(code)[seg * 16 + q] = c;
}

// ---------------- launch ----------------
extern "C" void kernel_launch(void* const* d_in, const int* in_sizes, int n_in,
                              void* d_out, int out_size) {
    const float* x     = (const float*)d_in[0];
    const float* W1    = (const float*)d_in[1];
    const float* b1    = (const float*)d_in[2];
    const float* theta = (const float*)d_in[3];
    const float* bias  = (const float*)d_in[4];
    const int*   hidx  = (const int*)d_in[5];
    const int* node = hidx;
    const int* edge = hidx + EE;

    float* out  = (float*)d_out;
    float* feat = out;
    float* hid  = out + (size_t)NN * HIDN;
    float* code = hid + (size_t)NN * CODEN;

    static bool attr_done = false;
    if (!attr_done) {
        cudaFuncSetAttribute(gemm1_h, cudaFuncAttributeMaxDynamicSharedMemorySize, G1_SMEM);
        cudaFuncSetAttribute(gemm2_h, cudaFuncAttributeMaxDynamicSharedMemorySize, G2_SMEM);
        attr_done = true;
    }

    // gemm1 placed early so the fixed ncu window (-s 5 -c 1) lands on it
    zero_kernel<<<(NN * CODEN + 255) / 256, 256>>>();
    round_x_h<<<(NN * (KP / 2) + 255) / 256, 256>>>(x);
    round_wt_h<<<dim3(KP / 32, HIDN / 32), dim3(32, 8)>>>(W1);
    gemm1_h<<<dim3(HIDN / 128, NN / 128), 128, G1_SMEM>>>(b1, feat);
    round_th_h<<<dim3(HIDN / 32, CODEN / 32), dim3(32, 8)>>>(theta);
    degree_kernel<<<(EE + 255) / 256, 256>>>(node, edge);
    scan_kernel<<<2, 1024>>>();
    fill_kernel<<<(EE + 255) / 256, 256>>>(node, edge);
    gemm2_h<<<dim3(4, NN / 128), 256, G2_SMEM>>>();
    gather1_kernel<<<NN / 16, 256>>>();
    gather2_kernel<<<NN / 16, 256>>>(hid, code, bias);
}